// round 14
// baseline (speedup 1.0000x reference)
#include <cuda_runtime.h>
#include <cuda_fp16.h>
#include <math.h>
#include <stdint.h>

#define BATCH 2048
#define IMG   28
#define HC    32
#define LC    16
#define WID   64
#define HID   64
#define LIS   22
#define FLAT  (LIS*LIS*HC)
#define BLK   (WID*LC)
#define OUT3  (3*BLK + WID)
#define NSTEP 20
#define NTAB  (2*NSTEP + 1)
#define NSM2  296               // 2 CTAs x 148 SMs

// ---------------- scratch ----------------
__device__ __half g_h0[(size_t)BATCH*676*32];   // conv0 out (26x26)
__device__ __half g_h1[(size_t)BATCH*576*32];   // conv1 out (24x24)
__device__ __half g_h2[(size_t)BATCH*484*32];   // conv2 out (22x22)
__device__ __half g_h3[(size_t)BATCH*784*32];   // t0 out padded (28x28); borders stay 0
__device__ __half g_h4[(size_t)BATCH*900*32];   // t1 out padded (30x30); borders stay 0
__device__ __half g_h5[(size_t)BATCH*676*32];   // decoder out padded (26x26); borders stay 0
__device__ float g_z1[BATCH*LC];
__device__ float g_val[BATCH];
__device__ float g_W [NTAB*WID*LC];   // [j][d][w]
__device__ float g_U [NTAB*WID*LC];   // [j][d][w]
__device__ float g_Bb[NTAB*WID];
__device__ float g_s [NTAB*WID];
__device__ float g_elwr[FLAT*LC];

// ---------------- helpers ----------------
__device__ __forceinline__ uint32_t smem_u32(const void* p) {
    uint32_t a;
    asm("{ .reg .u64 t; cvta.to.shared.u64 t, %1; cvt.u32.u64 %0, t; }" : "=r"(a) : "l"(p));
    return a;
}
__device__ __forceinline__ float tanha(float x) {
    asm("tanh.approx.f32 %0, %0;" : "+f"(x));
    return x;
}
__device__ __forceinline__ int swz(int row) { return (row ^ (row >> 2)) & 3; }

__device__ __forceinline__ void ldsm_x4(uint32_t& r0, uint32_t& r1, uint32_t& r2, uint32_t& r3,
                                        uint32_t addr) {
    asm volatile("ldmatrix.sync.aligned.m8n8.x4.shared.b16 {%0,%1,%2,%3}, [%4];"
        : "=r"(r0), "=r"(r1), "=r"(r2), "=r"(r3) : "r"(addr));
}
__device__ __forceinline__ void ldsm_x2t(uint32_t& r0, uint32_t& r1, uint32_t addr) {
    asm volatile("ldmatrix.sync.aligned.m8n8.x2.trans.shared.b16 {%0,%1}, [%2];"
        : "=r"(r0), "=r"(r1) : "r"(addr));
}
__device__ __forceinline__ void mma16816(float* d, uint32_t a0, uint32_t a1, uint32_t a2,
                                         uint32_t a3, uint32_t b0, uint32_t b1) {
    asm volatile(
        "mma.sync.aligned.m16n8k16.row.col.f32.f16.f16.f32 "
        "{%0,%1,%2,%3}, {%4,%5,%6,%7}, {%8,%9}, {%0,%1,%2,%3};"
        : "+f"(d[0]), "+f"(d[1]), "+f"(d[2]), "+f"(d[3])
        : "r"(a0), "r"(a1), "r"(a2), "r"(a3), "r"(b0), "r"(b1));
}

// =====================================================================
// convgemm PERSISTENT (round-13 winner, unchanged)
// =====================================================================
template<int PH, int PW, int OH, int OW, int NPH, int NPW, int NPAD, bool TRANS>
__global__ __launch_bounds__(256, 2)
void convgemm(const __half* __restrict__ in, const float* __restrict__ w,
              const float* __restrict__ bias, void* __restrict__ outv)
{
    constexpr int NO = OH * OW;
    constexpr int PASSES = (NO + 63) / 64;
    constexpr int INSZ = PH * PW * 64;
    constexpr int BOFF = INSZ;

    extern __shared__ char smem[];
    float* sbias = (float*)(smem + INSZ + 288 * 64);

    const int tid  = threadIdx.x;
    const int wrp  = tid >> 5;
    const int lane = tid & 31;
    const int mbase = (wrp >> 1) * 16;
    const int nh    = wrp & 1;

    const uint32_t sin = smem_u32(smem);
    const uint32_t sB  = sin + BOFF;

    // ---- B build ONCE per CTA ----
    for (int i = tid; i < 288 * 32; i += 256) {
        int k  = i >> 5;
        int oc = i & 31;
        int t  = k >> 5, ci = k & 31;
        int ky = t / 3, kx = t % 3;
        float v;
        if (TRANS) v = w[((ci * 32 + oc) * 3 + (2 - ky)) * 3 + (2 - kx)];
        else       v = w[((oc * 32 + ci) * 3 + ky) * 3 + kx];
        *(__half*)(smem + BOFF + k * 64 + (((oc >> 3) ^ swz(k)) << 4) + (oc & 7) * 2) =
            __float2half(v);
    }
    if (tid < 32) sbias[tid] = bias[tid];
    __syncthreads();

    // ---- B fragments ONCE per CTA ----
    uint32_t bf[18][2][2];
#pragma unroll
    for (int s = 0; s < 18; s++)
#pragma unroll
        for (int j = 0; j < 2; j++) {
            int kr = s * 16 + (lane & 15);
            uint32_t addr = sB + kr * 64 + ((((nh * 2 + j) ^ swz(kr))) << 4);
            ldsm_x2t(bf[s][j][0], bf[s][j][1], addr);
        }

    const int mrow_ld = (lane & 7) + ((lane >> 3) & 1) * 8;
    const int kc_hi   = lane >> 4;

#pragma unroll 1
    for (int n = blockIdx.x; n < BATCH; n += gridDim.x) {
        __syncthreads();
        {
            const uint4* ip = (const uint4*)(in + (size_t)n * PH * PW * 32);
            for (int i = tid; i < PH * PW * 4; i += 256) {
                int row = i >> 2, ch = i & 3;
                uint4 v = ip[i];
                *(uint4*)(smem + row * 64 + ((ch ^ swz(row)) << 4)) = v;
            }
        }
        __syncthreads();

#pragma unroll 1
        for (int pass = 0; pass < PASSES; pass++) {
            int p = pass * 64 + mbase + mrow_ld;
            if (p >= NO) p = 0;
            const int oy = p / OW, ox = p % OW;
            const int srow0 = oy * PW + ox;

            float acc[2][4];
#pragma unroll
            for (int j = 0; j < 2; j++)
#pragma unroll
                for (int q = 0; q < 4; q++) acc[j][q] = 0.f;

#pragma unroll
            for (int t = 0; t < 9; t++) {
                const int srow = srow0 + (t / 3) * PW + (t % 3);
                const uint32_t rb = sin + srow * 64;
                const int sz = swz(srow);
#pragma unroll
                for (int c = 0; c < 2; c++) {
                    uint32_t a0, a1, a2, a3;
                    ldsm_x4(a0, a1, a2, a3, rb + (((c * 2 + kc_hi) ^ sz) << 4));
                    const int s = t * 2 + c;
                    mma16816(acc[0], a0, a1, a2, a3, bf[s][0][0], bf[s][0][1]);
                    mma16816(acc[1], a0, a1, a2, a3, bf[s][1][0], bf[s][1][1]);
                }
            }

            const int prow = pass * 64 + mbase + (lane >> 2);
#pragma unroll
            for (int h = 0; h < 2; h++) {
                const int p2 = prow + h * 8;
                if (p2 < NO) {
                    const int oy2 = p2 / OW, ox2 = p2 % OW;
                    __half2* op = (__half2*)((__half*)outv
                        + (((size_t)n * NPH + oy2 + NPAD) * NPW + (ox2 + NPAD)) * 32);
#pragma unroll
                    for (int j = 0; j < 2; j++) {
                        const int oc = nh * 16 + j * 8 + (lane & 3) * 2;
                        float v0 = tanha(acc[j][h * 2]     + sbias[oc]);
                        float v1 = tanha(acc[j][h * 2 + 1] + sbias[oc + 1]);
                        op[oc >> 1] = __floats2half2_rn(v0, v1);
                    }
                }
            }
        }
    }
}

template<int PH, int PW, int OH, int OW, int NPH, int NPW, int NPAD, bool TRANS>
static void run_gemm(const __half* in, const float* w, const float* b, void* out)
{
    constexpr int bytes = PH * PW * 64 + 288 * 64 + 128;
    cudaFuncSetAttribute(convgemm<PH,PW,OH,OW,NPH,NPW,NPAD,TRANS>,
                         cudaFuncAttributeMaxDynamicSharedMemorySize, bytes);
    convgemm<PH,PW,OH,OW,NPH,NPW,NPAD,TRANS><<<NSM2, 256, bytes>>>(in, w, b, out);
}

// ---------------- t2: specialized convT 32->1 SIMT (lane = channel) ----------------
__global__ __launch_bounds__(256, 2)
void t2_kernel(const __half* __restrict__ in, const float* __restrict__ w,
               const float* __restrict__ bias, float* __restrict__ out)
{
    extern __shared__ char smz[];
    __half* stile = (__half*)smz;                       // 30*30*32 halves
    float*  swt   = (float*)(smz + 900 * 64);           // 32*9 flipped weights
    __shared__ float sb;

    const int n   = blockIdx.x;
    const int tid = threadIdx.x;
    const int wrp = tid >> 5, lane = tid & 31;

    {
        const uint4* ip = (const uint4*)(in + (size_t)n * 900 * 32);
        uint4* tp = (uint4*)stile;
        for (int i = tid; i < 900 * 4; i += 256) tp[i] = ip[i];
    }
    for (int i = tid; i < 288; i += 256) {
        int c = i / 9, k = i % 9, ky = k / 3, kx = k % 3;
        swt[i] = w[c * 9 + (2 - ky) * 3 + (2 - kx)];
    }
    if (tid == 0) sb = bias[0];
    __syncthreads();

    float wl[9];
#pragma unroll
    for (int k = 0; k < 9; k++) wl[k] = swt[lane * 9 + k];
    const float bb = sb;

#pragma unroll 1
    for (int px = wrp; px < 784; px += 8) {
        const int oy = px / 28, ox = px % 28;
        float a = 0.f;
#pragma unroll
        for (int k = 0; k < 9; k++) {
            int srow = (oy + k / 3) * 30 + ox + k % 3;
            a = fmaf(__half2float(stile[srow * 32 + lane]), wl[k], a);
        }
#pragma unroll
        for (int off = 16; off > 0; off >>= 1)
            a += __shfl_xor_sync(0xffffffffu, a, off);
        if (lane == 0) out[(size_t)n * 784 + px] = a + bb;
    }
}

// ---------------- conv0 ----------------
__global__ __launch_bounds__(256, 2)
void conv0_kernel(const float* __restrict__ x, const float* __restrict__ w,
                  const float* __restrict__ bias, __half* __restrict__ out)
{
    __shared__ float sx[784];
    __shared__ float sw[288];
    __shared__ float sb[32];
    const int n = blockIdx.x;
    const int tid = threadIdx.x;

    for (int i = tid; i < 784; i += 256) sx[i] = x[(size_t)n * 784 + i];
    for (int i = tid; i < 288; i += 256) sw[i] = w[i];
    if (tid < 32) sb[tid] = bias[tid];
    __syncthreads();

#pragma unroll 1
    for (int pix = tid; pix < 676; pix += 256) {
        int py = pix / 26, px = pix % 26;
        float v[9];
#pragma unroll
        for (int k = 0; k < 9; k++) v[k] = sx[(py + k / 3) * 28 + px + k % 3];
        uint4* op = (uint4*)(out + ((size_t)n * 676 + pix) * 32);
#pragma unroll 1
        for (int g = 0; g < 4; g++) {
            uint32_t h2[4];
#pragma unroll
            for (int j = 0; j < 4; j++) {
                const int c0 = g * 8 + 2 * j;
                float a = sb[c0], b = sb[c0 + 1];
#pragma unroll
                for (int k = 0; k < 9; k++) {
                    a = fmaf(v[k], sw[c0 * 9 + k], a);
                    b = fmaf(v[k], sw[(c0 + 1) * 9 + k], b);
                }
                a = tanha(a); b = tanha(b);
                asm("cvt.rn.f16x2.f32 %0, %1, %2;" : "=r"(h2[j]) : "f"(b), "f"(a));
            }
            op[g] = make_uint4(h2[0], h2[1], h2[2], h2[3]);
        }
    }
}

__global__ void repack_elw_kernel(const float* __restrict__ elw, float* __restrict__ out)
{
    const int N = FLAT * LC;
    for (int i = blockIdx.x * blockDim.x + threadIdx.x; i < N; i += gridDim.x * blockDim.x) {
        int fp = i / LC, l = i % LC;
        int pix = fp / 32, c = fp % 32;
        out[i] = elw[((size_t)(c * 484 + pix)) * LC + l];
    }
}

// ---------------- encoder ----------------
__global__ __launch_bounds__(256)
void encoder_kernel(const __half* __restrict__ h, const float* __restrict__ elwr,
                    const float* __restrict__ elb, float* __restrict__ z1)
{
    __shared__ float sw[128 * LC];
    __shared__ float sc[16 * 128];
    const int tid = threadIdx.x;
    const int n0  = blockIdx.x * 16;
    const int nl  = tid / LC;
    const int l   = tid % LC;

    float acc = 0.f;
    for (int fc = 0; fc < FLAT; fc += 128) {
        __syncthreads();
        for (int i = tid; i < 128 * LC; i += 256) sw[i] = elwr[(size_t)fc * LC + i];
        for (int i = tid; i < 16 * 128; i += 256) {
            int nn = i / 128, ff = i % 128;
            sc[i] = __half2float(h[(size_t)(n0 + nn) * FLAT + fc + ff]);
        }
        __syncthreads();
#pragma unroll 8
        for (int ff = 0; ff < 128; ff++)
            acc = fmaf(sc[nl * 128 + ff], sw[ff * LC + l], acc);
    }
    z1[(n0 + nl) * LC + l] = acc + elb[l];
}

// ---------------- decoder v1 (writes g_h5; borders stay zero) ----------------
__global__ __launch_bounds__(128)
void decoder_kernel(const float* __restrict__ z1, const float* __restrict__ dlw,
                    const float* __restrict__ dlb, __half* __restrict__ d)
{
    __shared__ float zs[16 * LC];
    const int tid = threadIdx.x;
    const int f   = blockIdx.x * 128 + tid;
    const int n0  = blockIdx.y * 16;

    for (int i = tid; i < 16 * LC; i += 128) zs[i] = z1[n0 * LC + i];
    __syncthreads();

    float wv[LC];
#pragma unroll
    for (int l = 0; l < LC; l++) wv[l] = dlw[(size_t)l * FLAT + f];
    const float bb = dlb[f];
    const int c = f / 484, pix = f % 484;
    const int py = pix / 22 + 2, px = pix % 22 + 2;

#pragma unroll
    for (int nn = 0; nn < 16; nn++) {
        float a = bb;
#pragma unroll
        for (int l = 0; l < LC; l++) a = fmaf(zs[nn * LC + l], wv[l], a);
        d[(((size_t)(n0 + nn) * 26 + py) * 26 + px) * 32 + c] = __float2half(tanha(a));
    }
}

// ---------------- hypernetwork tables ----------------
__global__ void hyper_kernel(const float* __restrict__ h1w, const float* __restrict__ h1b,
                             const float* __restrict__ h2w, const float* __restrict__ h2b,
                             const float* __restrict__ h3w, const float* __restrict__ h3b)
{
    const int j = blockIdx.x;
    const int w = threadIdx.x;
    const float t = 10.0f - 0.25f * (float)j;

    __shared__ float p1[HID], p2[HID];
    __shared__ float Wl[BLK], Ul[BLK];

    p1[w] = tanhf(t * h1w[w] + h1b[w]);
    __syncthreads();
    {
        float a = h2b[w];
#pragma unroll 8
        for (int k = 0; k < HID; k++) a = fmaf(p1[k], h2w[k * HID + w], a);
        p2[w] = tanhf(a);
    }
    __syncthreads();

    for (int o = w; o < OUT3; o += HID) {
        float a = h3b[o];
#pragma unroll 8
        for (int k = 0; k < HID; k++) a = fmaf(p2[k], h3w[(size_t)k * OUT3 + o], a);
        if (o < BLK)           Wl[o] = a;
        else if (o < 2 * BLK)  Ul[o - BLK] = a;
        else if (o < 3 * BLK)  Ul[o - 2 * BLK] *= 1.0f / (1.0f + expf(-a));
        else                   g_Bb[j * WID + (o - 3 * BLK)] = a;
    }
    __syncthreads();

    for (int o = w; o < BLK; o += HID) {
        int ww = o / LC, d = o % LC;
        g_W[j * BLK + d * WID + ww] = Wl[o];
        g_U[j * BLK + d * WID + ww] = Ul[o];
    }
    {
        float sv = 0.f;
#pragma unroll
        for (int d = 0; d < LC; d++) sv = fmaf(Wl[w * LC + d], Ul[w * LC + d], sv);
        g_s[j * WID + w] = sv;
    }
}

// ---------------- CNF RK4: 32 lanes per sample ----------------
__device__ __forceinline__ void feval32(int j, int lane, const float z[LC],
                                        float dz[LC], float& dl)
{
    const float* __restrict__ W  = g_W  + j * BLK;
    const float* __restrict__ U  = g_U  + j * BLK;
    const float* __restrict__ Bb = g_Bb + j * WID;
    const float* __restrict__ s  = g_s  + j * WID;
#pragma unroll
    for (int d = 0; d < LC; d++) dz[d] = 0.f;
    float tr = 0.f;
#pragma unroll
    for (int k = 0; k < 2; k++) {
        const int w = lane + k * 32;
        float a = Bb[w];
#pragma unroll
        for (int d = 0; d < LC; d++) a = fmaf(z[d], W[d * WID + w], a);
        float hh = tanhf(a);
#pragma unroll
        for (int d = 0; d < LC; d++) dz[d] = fmaf(hh, U[d * WID + w], dz[d]);
        tr = fmaf(1.0f - hh * hh, s[w], tr);
    }
#pragma unroll
    for (int off = 16; off > 0; off >>= 1) {
#pragma unroll
        for (int d = 0; d < LC; d++)
            dz[d] += __shfl_xor_sync(0xffffffffu, dz[d], off);
        tr += __shfl_xor_sync(0xffffffffu, tr, off);
    }
    const float inv = 1.0f / (float)WID;
#pragma unroll
    for (int d = 0; d < LC; d++) dz[d] *= inv;
    dl = -tr * inv;
}

__global__ __launch_bounds__(256)
void cnf_kernel(const float* __restrict__ z1, float* __restrict__ val)
{
    const int tid  = threadIdx.x;
    const int lane = tid & 31;
    const int n    = blockIdx.x * 8 + (tid >> 5);

    float z[LC];
#pragma unroll
    for (int d = 0; d < LC; d++) z[d] = z1[n * LC + d];
    float lp = 0.f;
    const float dt = -0.5f;

    for (int i = 0; i < NSTEP; i++) {
        float kz[LC], zt[LC], acc[LC];
        float l1, li, lacc;

        feval32(2 * i, lane, z, kz, l1);
        lacc = l1;
#pragma unroll
        for (int d = 0; d < LC; d++) { acc[d] = kz[d]; zt[d] = fmaf(0.5f * dt, kz[d], z[d]); }

        feval32(2 * i + 1, lane, zt, kz, li);
        lacc += 2.f * li;
#pragma unroll
        for (int d = 0; d < LC; d++) { acc[d] += 2.f * kz[d]; zt[d] = fmaf(0.5f * dt, kz[d], z[d]); }

        feval32(2 * i + 1, lane, zt, kz, li);
        lacc += 2.f * li;
#pragma unroll
        for (int d = 0; d < LC; d++) { acc[d] += 2.f * kz[d]; zt[d] = fmaf(dt, kz[d], z[d]); }

        feval32(2 * i + 2, lane, zt, kz, li);
        lacc += li;
#pragma unroll
        for (int d = 0; d < LC; d++) z[d] = fmaf(dt / 6.0f, acc[d] + kz[d], z[d]);
        lp = fmaf(dt / 6.0f, lacc, lp);
    }

    if (lane == 0) {
        float ss = 0.f;
#pragma unroll
        for (int d = 0; d < LC; d++) ss = fmaf(z[d], z[d], ss);
        const float c = (float)LC * 1.8378770664093453f + (float)LC * logf(0.1f);
        float logp = -0.5f * (c + ss * 10.0f);
        val[n] = logp - lp;
    }
}

__global__ __launch_bounds__(256)
void finalize_kernel(const float* __restrict__ val, float* __restrict__ outp)
{
    __shared__ float sm[256];
    const int tid = threadIdx.x;
    float a = 0.f;
    for (int i = tid; i < BATCH; i += 256) a += val[i];
    sm[tid] = a;
    __syncthreads();
    for (int s = 128; s > 0; s >>= 1) {
        if (tid < s) sm[tid] += sm[tid + s];
        __syncthreads();
    }
    if (tid == 0) outp[0] = sm[0] / (float)BATCH;
}

// ---------------- launcher ----------------
extern "C" void kernel_launch(void* const* d_in, const int* in_sizes, int n_in,
                              void* d_out, int out_size)
{
    const float* x   = (const float*)d_in[0];
    const float* c0w = (const float*)d_in[1];
    const float* c0b = (const float*)d_in[2];
    const float* c1w = (const float*)d_in[3];
    const float* c1b = (const float*)d_in[4];
    const float* c2w = (const float*)d_in[5];
    const float* c2b = (const float*)d_in[6];
    const float* elw = (const float*)d_in[7];
    const float* elb = (const float*)d_in[8];
    const float* dlw = (const float*)d_in[9];
    const float* dlb = (const float*)d_in[10];
    const float* t0w = (const float*)d_in[11];
    const float* t0b = (const float*)d_in[12];
    const float* t1w = (const float*)d_in[13];
    const float* t1b = (const float*)d_in[14];
    const float* t2w = (const float*)d_in[15];
    const float* t2b = (const float*)d_in[16];
    const float* h1w = (const float*)d_in[17];
    const float* h1b = (const float*)d_in[18];
    const float* h2w = (const float*)d_in[19];
    const float* h2b = (const float*)d_in[20];
    const float* h3w = (const float*)d_in[21];
    const float* h3b = (const float*)d_in[22];
    float* out = (float*)d_out;

    __half *h0, *h1, *h2, *h3, *h4, *h5;
    float *z1, *val, *elwr;
    cudaGetSymbolAddress((void**)&h0, g_h0);
    cudaGetSymbolAddress((void**)&h1, g_h1);
    cudaGetSymbolAddress((void**)&h2, g_h2);
    cudaGetSymbolAddress((void**)&h3, g_h3);
    cudaGetSymbolAddress((void**)&h4, g_h4);
    cudaGetSymbolAddress((void**)&h5, g_h5);
    cudaGetSymbolAddress((void**)&z1,  g_z1);
    cudaGetSymbolAddress((void**)&val, g_val);
    cudaGetSymbolAddress((void**)&elwr, g_elwr);

    hyper_kernel<<<NTAB, HID>>>(h1w, h1b, h2w, h2b, h3w, h3b);
    repack_elw_kernel<<<256, 256>>>(elw, elwr);

    // encoder path
    conv0_kernel<<<BATCH, 256>>>(x, c0w, c0b, h0);
    run_gemm<26,26,24,24, 24,24,0, false>(h0, c1w, c1b, h1);
    run_gemm<24,24,22,22, 22,22,0, false>(h1, c2w, c2b, h2);
    encoder_kernel<<<BATCH/16, 256>>>(h2, elwr, elb, z1);

    // CNF
    cnf_kernel<<<BATCH/8, 256>>>(z1, val);
    finalize_kernel<<<1, 256>>>(val, out + (size_t)BATCH*IMG*IMG);

    // decoder path (h5's pad frame is never written — stays zero)
    decoder_kernel<<<dim3(FLAT/128, BATCH/16), 128>>>(z1, dlw, dlb, h5);
    run_gemm<26,26,24,24, 28,28,2, true>(h5, t0w, t0b, h3);
    run_gemm<28,28,26,26, 30,30,2, true>(h3, t1w, t1b, h4);
    {
        constexpr int bytes = 900 * 64 + 288 * 4;
        cudaFuncSetAttribute(t2_kernel, cudaFuncAttributeMaxDynamicSharedMemorySize, bytes);
        t2_kernel<<<BATCH, 256, bytes>>>(h4, t2w, t2b, out);
    }
}

// round 15
// speedup vs baseline: 1.0456x; 1.0456x over previous
#include <cuda_runtime.h>
#include <cuda_fp16.h>
#include <math.h>
#include <stdint.h>

#define BATCH 2048
#define IMG   28
#define HC    32
#define LC    16
#define WID   64
#define HID   64
#define LIS   22
#define FLAT  (LIS*LIS*HC)
#define BLK   (WID*LC)
#define OUT3  (3*BLK + WID)
#define NSTEP 20
#define NTAB  (2*NSTEP + 1)
#define NSM2  296               // 2 CTAs x 148 SMs

// ---------------- scratch ----------------
__device__ __half g_h0[(size_t)BATCH*676*32];   // conv0 out (26x26)
__device__ __half g_h1[(size_t)BATCH*576*32];   // conv1 out (24x24)
__device__ __half g_h2[(size_t)BATCH*484*32];   // conv2 out (22x22)
__device__ __half g_h3[(size_t)BATCH*784*32];   // t0 out padded (28x28); borders stay 0
__device__ __half g_h4[(size_t)BATCH*900*32];   // t1 out padded (30x30); borders stay 0
__device__ __half g_h5[(size_t)BATCH*676*32];   // decoder out padded (26x26); borders stay 0
__device__ float g_z1[BATCH*LC];
__device__ float g_val[BATCH];
__device__ float g_W [NTAB*WID*LC];   // [j][d][w]
__device__ float g_U [NTAB*WID*LC];   // [j][d][w]
__device__ float g_Bb[NTAB*WID];
__device__ float g_s [NTAB*WID];
__device__ float g_elwr[FLAT*LC];

// ---------------- helpers ----------------
__device__ __forceinline__ uint32_t smem_u32(const void* p) {
    uint32_t a;
    asm("{ .reg .u64 t; cvta.to.shared.u64 t, %1; cvt.u32.u64 %0, t; }" : "=r"(a) : "l"(p));
    return a;
}
__device__ __forceinline__ float tanha(float x) {
    asm("tanh.approx.f32 %0, %0;" : "+f"(x));
    return x;
}
__device__ __forceinline__ int swz(int row) { return (row ^ (row >> 2)) & 3; }

__device__ __forceinline__ void ldsm_x4(uint32_t& r0, uint32_t& r1, uint32_t& r2, uint32_t& r3,
                                        uint32_t addr) {
    asm volatile("ldmatrix.sync.aligned.m8n8.x4.shared.b16 {%0,%1,%2,%3}, [%4];"
        : "=r"(r0), "=r"(r1), "=r"(r2), "=r"(r3) : "r"(addr));
}
__device__ __forceinline__ void ldsm_x2t(uint32_t& r0, uint32_t& r1, uint32_t addr) {
    asm volatile("ldmatrix.sync.aligned.m8n8.x2.trans.shared.b16 {%0,%1}, [%2];"
        : "=r"(r0), "=r"(r1) : "r"(addr));
}
__device__ __forceinline__ void mma16816(float* d, uint32_t a0, uint32_t a1, uint32_t a2,
                                         uint32_t a3, uint32_t b0, uint32_t b1) {
    asm volatile(
        "mma.sync.aligned.m16n8k16.row.col.f32.f16.f16.f32 "
        "{%0,%1,%2,%3}, {%4,%5,%6,%7}, {%8,%9}, {%0,%1,%2,%3};"
        : "+f"(d[0]), "+f"(d[1]), "+f"(d[2]), "+f"(d[3])
        : "r"(a0), "r"(a1), "r"(a2), "r"(a3), "r"(b0), "r"(b1));
}

// =====================================================================
// convgemm PERSISTENT. Normal: 8 warps = 4 m-tiles x 2 n-halves (N=32).
// LAST (t2, COUT=1): 8 warps = 8 m-tiles, N=8 (single n-tile with oc0),
// 1 MMA per k-step instead of 4 -> ~4x less tensor work.
// =====================================================================
template<int PH, int PW, int OH, int OW, int NPH, int NPW, int NPAD, bool TRANS, bool LAST>
__global__ __launch_bounds__(256, 2)
void convgemm(const __half* __restrict__ in, const float* __restrict__ w,
              const float* __restrict__ bias, void* __restrict__ outv)
{
    constexpr int NO = OH * OW;
    constexpr int MW = LAST ? 8 : 4;                 // m-tiles per pass
    constexpr int PPASS = MW * 16;                   // pixels per pass
    constexpr int PASSES = (NO + PPASS - 1) / PPASS;
    constexpr int NJ = LAST ? 1 : 2;                 // n8-tiles per warp
    constexpr int INSZ = PH * PW * 64;
    constexpr int BOFF = INSZ;

    extern __shared__ char smem[];
    float* sbias = (float*)(smem + INSZ + 288 * 64);

    const int tid  = threadIdx.x;
    const int wrp  = tid >> 5;
    const int lane = tid & 31;
    const int mbase = LAST ? wrp * 16 : (wrp >> 1) * 16;
    const int nh    = LAST ? 0 : (wrp & 1);

    const uint32_t sin = smem_u32(smem);
    const uint32_t sB  = sin + BOFF;

    // ---- B build ONCE per CTA ----
    for (int i = tid; i < 288 * 32; i += 256) {
        int k  = i >> 5;
        int oc = i & 31;
        int t  = k >> 5, ci = k & 31;
        int ky = t / 3, kx = t % 3;
        float v;
        if (LAST)       v = (oc == 0) ? w[ci * 9 + (2 - ky) * 3 + (2 - kx)] : 0.f;
        else if (TRANS) v = w[((ci * 32 + oc) * 3 + (2 - ky)) * 3 + (2 - kx)];
        else            v = w[((oc * 32 + ci) * 3 + ky) * 3 + kx];
        *(__half*)(smem + BOFF + k * 64 + (((oc >> 3) ^ swz(k)) << 4) + (oc & 7) * 2) =
            __float2half(v);
    }
    if (tid < 32) sbias[tid] = LAST ? (tid == 0 ? bias[0] : 0.f) : bias[tid];
    __syncthreads();

    // ---- B fragments ONCE per CTA ----
    uint32_t bf[18][NJ][2];
#pragma unroll
    for (int s = 0; s < 18; s++)
#pragma unroll
        for (int j = 0; j < NJ; j++) {
            int kr = s * 16 + (lane & 15);
            uint32_t addr = sB + kr * 64 + ((((nh * 2 + j) ^ swz(kr))) << 4);
            ldsm_x2t(bf[s][j][0], bf[s][j][1], addr);
        }

    const int mrow_ld = (lane & 7) + ((lane >> 3) & 1) * 8;
    const int kc_hi   = lane >> 4;

#pragma unroll 1
    for (int n = blockIdx.x; n < BATCH; n += gridDim.x) {
        __syncthreads();
        {
            const uint4* ip = (const uint4*)(in + (size_t)n * PH * PW * 32);
            for (int i = tid; i < PH * PW * 4; i += 256) {
                int row = i >> 2, ch = i & 3;
                uint4 v = ip[i];
                *(uint4*)(smem + row * 64 + ((ch ^ swz(row)) << 4)) = v;
            }
        }
        __syncthreads();

#pragma unroll 1
        for (int pass = 0; pass < PASSES; pass++) {
            int p = pass * PPASS + mbase + mrow_ld;
            if (p >= NO) p = 0;
            const int oy = p / OW, ox = p % OW;
            const int srow0 = oy * PW + ox;

            float acc[NJ][4];
#pragma unroll
            for (int j = 0; j < NJ; j++)
#pragma unroll
                for (int q = 0; q < 4; q++) acc[j][q] = 0.f;

#pragma unroll
            for (int t = 0; t < 9; t++) {
                const int srow = srow0 + (t / 3) * PW + (t % 3);
                const uint32_t rb = sin + srow * 64;
                const int sz = swz(srow);
#pragma unroll
                for (int c = 0; c < 2; c++) {
                    uint32_t a0, a1, a2, a3;
                    ldsm_x4(a0, a1, a2, a3, rb + (((c * 2 + kc_hi) ^ sz) << 4));
                    const int s = t * 2 + c;
#pragma unroll
                    for (int j = 0; j < NJ; j++)
                        mma16816(acc[j], a0, a1, a2, a3, bf[s][j][0], bf[s][j][1]);
                }
            }

            const int prow = pass * PPASS + mbase + (lane >> 2);
#pragma unroll
            for (int h = 0; h < 2; h++) {
                const int p2 = prow + h * 8;
                if (p2 < NO) {
                    if (LAST) {
                        if ((lane & 3) == 0)
                            ((float*)outv)[(size_t)n * NO + p2] = acc[0][h * 2] + sbias[0];
                    } else {
                        const int oy2 = p2 / OW, ox2 = p2 % OW;
                        __half2* op = (__half2*)((__half*)outv
                            + (((size_t)n * NPH + oy2 + NPAD) * NPW + (ox2 + NPAD)) * 32);
#pragma unroll
                        for (int j = 0; j < NJ; j++) {
                            const int oc = nh * 16 + j * 8 + (lane & 3) * 2;
                            float v0 = tanha(acc[j][h * 2]     + sbias[oc]);
                            float v1 = tanha(acc[j][h * 2 + 1] + sbias[oc + 1]);
                            op[oc >> 1] = __floats2half2_rn(v0, v1);
                        }
                    }
                }
            }
        }
    }
}

template<int PH, int PW, int OH, int OW, int NPH, int NPW, int NPAD, bool TRANS, bool LAST>
static void run_gemm(const __half* in, const float* w, const float* b, void* out)
{
    constexpr int bytes = PH * PW * 64 + 288 * 64 + 128;
    cudaFuncSetAttribute(convgemm<PH,PW,OH,OW,NPH,NPW,NPAD,TRANS,LAST>,
                         cudaFuncAttributeMaxDynamicSharedMemorySize, bytes);
    convgemm<PH,PW,OH,OW,NPH,NPW,NPAD,TRANS,LAST><<<NSM2, 256, bytes>>>(in, w, b, out);
}

// ---------------- conv0 ----------------
__global__ __launch_bounds__(256, 2)
void conv0_kernel(const float* __restrict__ x, const float* __restrict__ w,
                  const float* __restrict__ bias, __half* __restrict__ out)
{
    __shared__ float sx[784];
    __shared__ float sw[288];
    __shared__ float sb[32];
    const int n = blockIdx.x;
    const int tid = threadIdx.x;

    for (int i = tid; i < 784; i += 256) sx[i] = x[(size_t)n * 784 + i];
    for (int i = tid; i < 288; i += 256) sw[i] = w[i];
    if (tid < 32) sb[tid] = bias[tid];
    __syncthreads();

#pragma unroll 1
    for (int pix = tid; pix < 676; pix += 256) {
        int py = pix / 26, px = pix % 26;
        float v[9];
#pragma unroll
        for (int k = 0; k < 9; k++) v[k] = sx[(py + k / 3) * 28 + px + k % 3];
        uint4* op = (uint4*)(out + ((size_t)n * 676 + pix) * 32);
#pragma unroll 1
        for (int g = 0; g < 4; g++) {
            uint32_t h2[4];
#pragma unroll
            for (int j = 0; j < 4; j++) {
                const int c0 = g * 8 + 2 * j;
                float a = sb[c0], b = sb[c0 + 1];
#pragma unroll
                for (int k = 0; k < 9; k++) {
                    a = fmaf(v[k], sw[c0 * 9 + k], a);
                    b = fmaf(v[k], sw[(c0 + 1) * 9 + k], b);
                }
                a = tanha(a); b = tanha(b);
                asm("cvt.rn.f16x2.f32 %0, %1, %2;" : "=r"(h2[j]) : "f"(b), "f"(a));
            }
            op[g] = make_uint4(h2[0], h2[1], h2[2], h2[3]);
        }
    }
}

__global__ void repack_elw_kernel(const float* __restrict__ elw, float* __restrict__ out)
{
    const int N = FLAT * LC;
    for (int i = blockIdx.x * blockDim.x + threadIdx.x; i < N; i += gridDim.x * blockDim.x) {
        int fp = i / LC, l = i % LC;
        int pix = fp / 32, c = fp % 32;
        out[i] = elw[((size_t)(c * 484 + pix)) * LC + l];
    }
}

// ---------------- encoder ----------------
__global__ __launch_bounds__(256)
void encoder_kernel(const __half* __restrict__ h, const float* __restrict__ elwr,
                    const float* __restrict__ elb, float* __restrict__ z1)
{
    __shared__ float sw[128 * LC];
    __shared__ float sc[16 * 128];
    const int tid = threadIdx.x;
    const int n0  = blockIdx.x * 16;
    const int nl  = tid / LC;
    const int l   = tid % LC;

    float acc = 0.f;
    for (int fc = 0; fc < FLAT; fc += 128) {
        __syncthreads();
        for (int i = tid; i < 128 * LC; i += 256) sw[i] = elwr[(size_t)fc * LC + i];
        for (int i = tid; i < 16 * 128; i += 256) {
            int nn = i / 128, ff = i % 128;
            sc[i] = __half2float(h[(size_t)(n0 + nn) * FLAT + fc + ff]);
        }
        __syncthreads();
#pragma unroll 8
        for (int ff = 0; ff < 128; ff++)
            acc = fmaf(sc[nl * 128 + ff], sw[ff * LC + l], acc);
    }
    z1[(n0 + nl) * LC + l] = acc + elb[l];
}

// ---------------- decoder v1 (writes g_h5; borders stay zero) ----------------
__global__ __launch_bounds__(128)
void decoder_kernel(const float* __restrict__ z1, const float* __restrict__ dlw,
                    const float* __restrict__ dlb, __half* __restrict__ d)
{
    __shared__ float zs[16 * LC];
    const int tid = threadIdx.x;
    const int f   = blockIdx.x * 128 + tid;
    const int n0  = blockIdx.y * 16;

    for (int i = tid; i < 16 * LC; i += 128) zs[i] = z1[n0 * LC + i];
    __syncthreads();

    float wv[LC];
#pragma unroll
    for (int l = 0; l < LC; l++) wv[l] = dlw[(size_t)l * FLAT + f];
    const float bb = dlb[f];
    const int c = f / 484, pix = f % 484;
    const int py = pix / 22 + 2, px = pix % 22 + 2;

#pragma unroll
    for (int nn = 0; nn < 16; nn++) {
        float a = bb;
#pragma unroll
        for (int l = 0; l < LC; l++) a = fmaf(zs[nn * LC + l], wv[l], a);
        d[(((size_t)(n0 + nn) * 26 + py) * 26 + px) * 32 + c] = __float2half(tanha(a));
    }
}

// ---------------- hypernetwork tables ----------------
__global__ void hyper_kernel(const float* __restrict__ h1w, const float* __restrict__ h1b,
                             const float* __restrict__ h2w, const float* __restrict__ h2b,
                             const float* __restrict__ h3w, const float* __restrict__ h3b)
{
    const int j = blockIdx.x;
    const int w = threadIdx.x;
    const float t = 10.0f - 0.25f * (float)j;

    __shared__ float p1[HID], p2[HID];
    __shared__ float Wl[BLK], Ul[BLK];

    p1[w] = tanhf(t * h1w[w] + h1b[w]);
    __syncthreads();
    {
        float a = h2b[w];
#pragma unroll 8
        for (int k = 0; k < HID; k++) a = fmaf(p1[k], h2w[k * HID + w], a);
        p2[w] = tanhf(a);
    }
    __syncthreads();

    for (int o = w; o < OUT3; o += HID) {
        float a = h3b[o];
#pragma unroll 8
        for (int k = 0; k < HID; k++) a = fmaf(p2[k], h3w[(size_t)k * OUT3 + o], a);
        if (o < BLK)           Wl[o] = a;
        else if (o < 2 * BLK)  Ul[o - BLK] = a;
        else if (o < 3 * BLK)  Ul[o - 2 * BLK] *= 1.0f / (1.0f + expf(-a));
        else                   g_Bb[j * WID + (o - 3 * BLK)] = a;
    }
    __syncthreads();

    for (int o = w; o < BLK; o += HID) {
        int ww = o / LC, d = o % LC;
        g_W[j * BLK + d * WID + ww] = Wl[o];
        g_U[j * BLK + d * WID + ww] = Ul[o];
    }
    {
        float sv = 0.f;
#pragma unroll
        for (int d = 0; d < LC; d++) sv = fmaf(Wl[w * LC + d], Ul[w * LC + d], sv);
        g_s[j * WID + w] = sv;
    }
}

// ---------------- CNF RK4: 32 lanes per sample ----------------
__device__ __forceinline__ void feval32(int j, int lane, const float z[LC],
                                        float dz[LC], float& dl)
{
    const float* __restrict__ W  = g_W  + j * BLK;
    const float* __restrict__ U  = g_U  + j * BLK;
    const float* __restrict__ Bb = g_Bb + j * WID;
    const float* __restrict__ s  = g_s  + j * WID;
#pragma unroll
    for (int d = 0; d < LC; d++) dz[d] = 0.f;
    float tr = 0.f;
#pragma unroll
    for (int k = 0; k < 2; k++) {
        const int w = lane + k * 32;
        float a = Bb[w];
#pragma unroll
        for (int d = 0; d < LC; d++) a = fmaf(z[d], W[d * WID + w], a);
        float hh = tanhf(a);
#pragma unroll
        for (int d = 0; d < LC; d++) dz[d] = fmaf(hh, U[d * WID + w], dz[d]);
        tr = fmaf(1.0f - hh * hh, s[w], tr);
    }
#pragma unroll
    for (int off = 16; off > 0; off >>= 1) {
#pragma unroll
        for (int d = 0; d < LC; d++)
            dz[d] += __shfl_xor_sync(0xffffffffu, dz[d], off);
        tr += __shfl_xor_sync(0xffffffffu, tr, off);
    }
    const float inv = 1.0f / (float)WID;
#pragma unroll
    for (int d = 0; d < LC; d++) dz[d] *= inv;
    dl = -tr * inv;
}

__global__ __launch_bounds__(256)
void cnf_kernel(const float* __restrict__ z1, float* __restrict__ val)
{
    const int tid  = threadIdx.x;
    const int lane = tid & 31;
    const int n    = blockIdx.x * 8 + (tid >> 5);

    float z[LC];
#pragma unroll
    for (int d = 0; d < LC; d++) z[d] = z1[n * LC + d];
    float lp = 0.f;
    const float dt = -0.5f;

    for (int i = 0; i < NSTEP; i++) {
        float kz[LC], zt[LC], acc[LC];
        float l1, li, lacc;

        feval32(2 * i, lane, z, kz, l1);
        lacc = l1;
#pragma unroll
        for (int d = 0; d < LC; d++) { acc[d] = kz[d]; zt[d] = fmaf(0.5f * dt, kz[d], z[d]); }

        feval32(2 * i + 1, lane, zt, kz, li);
        lacc += 2.f * li;
#pragma unroll
        for (int d = 0; d < LC; d++) { acc[d] += 2.f * kz[d]; zt[d] = fmaf(0.5f * dt, kz[d], z[d]); }

        feval32(2 * i + 1, lane, zt, kz, li);
        lacc += 2.f * li;
#pragma unroll
        for (int d = 0; d < LC; d++) { acc[d] += 2.f * kz[d]; zt[d] = fmaf(dt, kz[d], z[d]); }

        feval32(2 * i + 2, lane, zt, kz, li);
        lacc += li;
#pragma unroll
        for (int d = 0; d < LC; d++) z[d] = fmaf(dt / 6.0f, acc[d] + kz[d], z[d]);
        lp = fmaf(dt / 6.0f, lacc, lp);
    }

    if (lane == 0) {
        float ss = 0.f;
#pragma unroll
        for (int d = 0; d < LC; d++) ss = fmaf(z[d], z[d], ss);
        const float c = (float)LC * 1.8378770664093453f + (float)LC * logf(0.1f);
        float logp = -0.5f * (c + ss * 10.0f);
        val[n] = logp - lp;
    }
}

__global__ __launch_bounds__(256)
void finalize_kernel(const float* __restrict__ val, float* __restrict__ outp)
{
    __shared__ float sm[256];
    const int tid = threadIdx.x;
    float a = 0.f;
    for (int i = tid; i < BATCH; i += 256) a += val[i];
    sm[tid] = a;
    __syncthreads();
    for (int s = 128; s > 0; s >>= 1) {
        if (tid < s) sm[tid] += sm[tid + s];
        __syncthreads();
    }
    if (tid == 0) outp[0] = sm[0] / (float)BATCH;
}

// ---------------- launcher ----------------
extern "C" void kernel_launch(void* const* d_in, const int* in_sizes, int n_in,
                              void* d_out, int out_size)
{
    const float* x   = (const float*)d_in[0];
    const float* c0w = (const float*)d_in[1];
    const float* c0b = (const float*)d_in[2];
    const float* c1w = (const float*)d_in[3];
    const float* c1b = (const float*)d_in[4];
    const float* c2w = (const float*)d_in[5];
    const float* c2b = (const float*)d_in[6];
    const float* elw = (const float*)d_in[7];
    const float* elb = (const float*)d_in[8];
    const float* dlw = (const float*)d_in[9];
    const float* dlb = (const float*)d_in[10];
    const float* t0w = (const float*)d_in[11];
    const float* t0b = (const float*)d_in[12];
    const float* t1w = (const float*)d_in[13];
    const float* t1b = (const float*)d_in[14];
    const float* t2w = (const float*)d_in[15];
    const float* t2b = (const float*)d_in[16];
    const float* h1w = (const float*)d_in[17];
    const float* h1b = (const float*)d_in[18];
    const float* h2w = (const float*)d_in[19];
    const float* h2b = (const float*)d_in[20];
    const float* h3w = (const float*)d_in[21];
    const float* h3b = (const float*)d_in[22];
    float* out = (float*)d_out;

    __half *h0, *h1, *h2, *h3, *h4, *h5;
    float *z1, *val, *elwr;
    cudaGetSymbolAddress((void**)&h0, g_h0);
    cudaGetSymbolAddress((void**)&h1, g_h1);
    cudaGetSymbolAddress((void**)&h2, g_h2);
    cudaGetSymbolAddress((void**)&h3, g_h3);
    cudaGetSymbolAddress((void**)&h4, g_h4);
    cudaGetSymbolAddress((void**)&h5, g_h5);
    cudaGetSymbolAddress((void**)&z1,  g_z1);
    cudaGetSymbolAddress((void**)&val, g_val);
    cudaGetSymbolAddress((void**)&elwr, g_elwr);

    hyper_kernel<<<NTAB, HID>>>(h1w, h1b, h2w, h2b, h3w, h3b);
    repack_elw_kernel<<<256, 256>>>(elw, elwr);

    // encoder path
    conv0_kernel<<<BATCH, 256>>>(x, c0w, c0b, h0);
    run_gemm<26,26,24,24, 24,24,0, false,false>(h0, c1w, c1b, h1);
    run_gemm<24,24,22,22, 22,22,0, false,false>(h1, c2w, c2b, h2);
    encoder_kernel<<<BATCH/16, 256>>>(h2, elwr, elb, z1);

    // CNF
    cnf_kernel<<<BATCH/8, 256>>>(z1, val);
    finalize_kernel<<<1, 256>>>(val, out + (size_t)BATCH*IMG*IMG);

    // decoder path (h5's pad frame never written — stays zero)
    decoder_kernel<<<dim3(FLAT/128, BATCH/16), 128>>>(z1, dlw, dlb, h5);
    run_gemm<26,26,24,24, 28,28,2, true,false>(h5, t0w, t0b, h3);
    run_gemm<28,28,26,26, 30,30,2, true,false>(h3, t1w, t1b, h4);
    run_gemm<30,30,28,28, 0,0,0,   true,true >(h4, t2w, t2b, out);
}

// round 17
// speedup vs baseline: 1.3908x; 1.3301x over previous
#include <cuda_runtime.h>
#include <cuda_fp16.h>
#include <math.h>
#include <stdint.h>

#define BATCH 2048
#define IMG   28
#define HC    32
#define LC    16
#define WID   64
#define HID   64
#define LIS   22
#define FLAT  (LIS*LIS*HC)
#define BLK   (WID*LC)
#define OUT3  (3*BLK + WID)
#define NSTEP 20
#define NTAB  (2*NSTEP + 1)
#define NSM2  296               // 2 CTAs x 148 SMs

// ---------------- scratch ----------------
__device__ __half g_h0[(size_t)BATCH*676*32];   // conv0 out (26x26)
__device__ __half g_h1[(size_t)BATCH*576*32];   // conv1 out (24x24)
__device__ __half g_h2[(size_t)BATCH*484*32];   // conv2 out (22x22)
__device__ __half g_h3[(size_t)BATCH*784*32];   // t0 out padded (28x28); borders stay 0
__device__ __half g_h4[(size_t)BATCH*900*32];   // t1 out padded (30x30); borders stay 0
__device__ __half g_h5[(size_t)BATCH*676*32];   // decoder out padded (26x26); borders stay 0
__device__ float g_z1[BATCH*LC];
__device__ float g_z1p[4*BATCH*LC];             // encoder split-K partials
__device__ float g_val[BATCH];
__device__ float g_W [NTAB*WID*LC];   // [j][d][w]
__device__ float g_U [NTAB*WID*LC];   // [j][d][w]
__device__ float g_Bb[NTAB*WID];
__device__ float g_s [NTAB*WID];
__device__ float g_elwr[FLAT*LC];

// ---------------- helpers ----------------
__device__ __forceinline__ uint32_t smem_u32(const void* p) {
    uint32_t a;
    asm("{ .reg .u64 t; cvta.to.shared.u64 t, %1; cvt.u32.u64 %0, t; }" : "=r"(a) : "l"(p));
    return a;
}
__device__ __forceinline__ float tanha(float x) {
    asm("tanh.approx.f32 %0, %0;" : "+f"(x));
    return x;
}
__device__ __forceinline__ int swz(int row) { return (row ^ (row >> 2)) & 3; }

__device__ __forceinline__ void ldsm_x4(uint32_t& r0, uint32_t& r1, uint32_t& r2, uint32_t& r3,
                                        uint32_t addr) {
    asm volatile("ldmatrix.sync.aligned.m8n8.x4.shared.b16 {%0,%1,%2,%3}, [%4];"
        : "=r"(r0), "=r"(r1), "=r"(r2), "=r"(r3) : "r"(addr));
}
__device__ __forceinline__ void ldsm_x2t(uint32_t& r0, uint32_t& r1, uint32_t addr) {
    asm volatile("ldmatrix.sync.aligned.m8n8.x2.trans.shared.b16 {%0,%1}, [%2];"
        : "=r"(r0), "=r"(r1) : "r"(addr));
}
__device__ __forceinline__ void mma16816(float* d, uint32_t a0, uint32_t a1, uint32_t a2,
                                         uint32_t a3, uint32_t b0, uint32_t b1) {
    asm volatile(
        "mma.sync.aligned.m16n8k16.row.col.f32.f16.f16.f32 "
        "{%0,%1,%2,%3}, {%4,%5,%6,%7}, {%8,%9}, {%0,%1,%2,%3};"
        : "+f"(d[0]), "+f"(d[1]), "+f"(d[2]), "+f"(d[3])
        : "r"(a0), "r"(a1), "r"(a2), "r"(a3), "r"(b0), "r"(b1));
}

// =====================================================================
// convgemm PERSISTENT (round-15 winner, unchanged)
// =====================================================================
template<int PH, int PW, int OH, int OW, int NPH, int NPW, int NPAD, bool TRANS, bool LAST>
__global__ __launch_bounds__(256, 2)
void convgemm(const __half* __restrict__ in, const float* __restrict__ w,
              const float* __restrict__ bias, void* __restrict__ outv)
{
    constexpr int NO = OH * OW;
    constexpr int MW = LAST ? 8 : 4;
    constexpr int PPASS = MW * 16;
    constexpr int PASSES = (NO + PPASS - 1) / PPASS;
    constexpr int NJ = LAST ? 1 : 2;
    constexpr int INSZ = PH * PW * 64;
    constexpr int BOFF = INSZ;

    extern __shared__ char smem[];
    float* sbias = (float*)(smem + INSZ + 288 * 64);

    const int tid  = threadIdx.x;
    const int wrp  = tid >> 5;
    const int lane = tid & 31;
    const int mbase = LAST ? wrp * 16 : (wrp >> 1) * 16;
    const int nh    = LAST ? 0 : (wrp & 1);

    const uint32_t sin = smem_u32(smem);
    const uint32_t sB  = sin + BOFF;

    for (int i = tid; i < 288 * 32; i += 256) {
        int k  = i >> 5;
        int oc = i & 31;
        int t  = k >> 5, ci = k & 31;
        int ky = t / 3, kx = t % 3;
        float v;
        if (LAST)       v = (oc == 0) ? w[ci * 9 + (2 - ky) * 3 + (2 - kx)] : 0.f;
        else if (TRANS) v = w[((ci * 32 + oc) * 3 + (2 - ky)) * 3 + (2 - kx)];
        else            v = w[((oc * 32 + ci) * 3 + ky) * 3 + kx];
        *(__half*)(smem + BOFF + k * 64 + (((oc >> 3) ^ swz(k)) << 4) + (oc & 7) * 2) =
            __float2half(v);
    }
    if (tid < 32) sbias[tid] = LAST ? (tid == 0 ? bias[0] : 0.f) : bias[tid];
    __syncthreads();

    uint32_t bf[18][NJ][2];
#pragma unroll
    for (int s = 0; s < 18; s++)
#pragma unroll
        for (int j = 0; j < NJ; j++) {
            int kr = s * 16 + (lane & 15);
            uint32_t addr = sB + kr * 64 + ((((nh * 2 + j) ^ swz(kr))) << 4);
            ldsm_x2t(bf[s][j][0], bf[s][j][1], addr);
        }

    const int mrow_ld = (lane & 7) + ((lane >> 3) & 1) * 8;
    const int kc_hi   = lane >> 4;

#pragma unroll 1
    for (int n = blockIdx.x; n < BATCH; n += gridDim.x) {
        __syncthreads();
        {
            const uint4* ip = (const uint4*)(in + (size_t)n * PH * PW * 32);
            for (int i = tid; i < PH * PW * 4; i += 256) {
                int row = i >> 2, ch = i & 3;
                uint4 v = ip[i];
                *(uint4*)(smem + row * 64 + ((ch ^ swz(row)) << 4)) = v;
            }
        }
        __syncthreads();

#pragma unroll 1
        for (int pass = 0; pass < PASSES; pass++) {
            int p = pass * PPASS + mbase + mrow_ld;
            if (p >= NO) p = 0;
            const int oy = p / OW, ox = p % OW;
            const int srow0 = oy * PW + ox;

            float acc[NJ][4];
#pragma unroll
            for (int j = 0; j < NJ; j++)
#pragma unroll
                for (int q = 0; q < 4; q++) acc[j][q] = 0.f;

#pragma unroll
            for (int t = 0; t < 9; t++) {
                const int srow = srow0 + (t / 3) * PW + (t % 3);
                const uint32_t rb = sin + srow * 64;
                const int sz = swz(srow);
#pragma unroll
                for (int c = 0; c < 2; c++) {
                    uint32_t a0, a1, a2, a3;
                    ldsm_x4(a0, a1, a2, a3, rb + (((c * 2 + kc_hi) ^ sz) << 4));
                    const int s = t * 2 + c;
#pragma unroll
                    for (int j = 0; j < NJ; j++)
                        mma16816(acc[j], a0, a1, a2, a3, bf[s][j][0], bf[s][j][1]);
                }
            }

            const int prow = pass * PPASS + mbase + (lane >> 2);
#pragma unroll
            for (int h = 0; h < 2; h++) {
                const int p2 = prow + h * 8;
                if (p2 < NO) {
                    if (LAST) {
                        if ((lane & 3) == 0)
                            ((float*)outv)[(size_t)n * NO + p2] = acc[0][h * 2] + sbias[0];
                    } else {
                        const int oy2 = p2 / OW, ox2 = p2 % OW;
                        __half2* op = (__half2*)((__half*)outv
                            + (((size_t)n * NPH + oy2 + NPAD) * NPW + (ox2 + NPAD)) * 32);
#pragma unroll
                        for (int j = 0; j < NJ; j++) {
                            const int oc = nh * 16 + j * 8 + (lane & 3) * 2;
                            float v0 = tanha(acc[j][h * 2]     + sbias[oc]);
                            float v1 = tanha(acc[j][h * 2 + 1] + sbias[oc + 1]);
                            op[oc >> 1] = __floats2half2_rn(v0, v1);
                        }
                    }
                }
            }
        }
    }
}

template<int PH, int PW, int OH, int OW, int NPH, int NPW, int NPAD, bool TRANS, bool LAST>
static void run_gemm(const __half* in, const float* w, const float* b, void* out,
                     cudaStream_t st)
{
    constexpr int bytes = PH * PW * 64 + 288 * 64 + 128;
    cudaFuncSetAttribute(convgemm<PH,PW,OH,OW,NPH,NPW,NPAD,TRANS,LAST>,
                         cudaFuncAttributeMaxDynamicSharedMemorySize, bytes);
    convgemm<PH,PW,OH,OW,NPH,NPW,NPAD,TRANS,LAST><<<NSM2, 256, bytes, st>>>(in, w, b, out);
}

// ---------------- conv0 ----------------
__global__ __launch_bounds__(256, 2)
void conv0_kernel(const float* __restrict__ x, const float* __restrict__ w,
                  const float* __restrict__ bias, __half* __restrict__ out)
{
    __shared__ float sx[784];
    __shared__ float sw[288];
    __shared__ float sb[32];
    const int n = blockIdx.x;
    const int tid = threadIdx.x;

    for (int i = tid; i < 784; i += 256) sx[i] = x[(size_t)n * 784 + i];
    for (int i = tid; i < 288; i += 256) sw[i] = w[i];
    if (tid < 32) sb[tid] = bias[tid];
    __syncthreads();

#pragma unroll 1
    for (int pix = tid; pix < 676; pix += 256) {
        int py = pix / 26, px = pix % 26;
        float v[9];
#pragma unroll
        for (int k = 0; k < 9; k++) v[k] = sx[(py + k / 3) * 28 + px + k % 3];
        uint4* op = (uint4*)(out + ((size_t)n * 676 + pix) * 32);
#pragma unroll 1
        for (int g = 0; g < 4; g++) {
            uint32_t h2[4];
#pragma unroll
            for (int j = 0; j < 4; j++) {
                const int c0 = g * 8 + 2 * j;
                float a = sb[c0], b = sb[c0 + 1];
#pragma unroll
                for (int k = 0; k < 9; k++) {
                    a = fmaf(v[k], sw[c0 * 9 + k], a);
                    b = fmaf(v[k], sw[(c0 + 1) * 9 + k], b);
                }
                a = tanha(a); b = tanha(b);
                asm("cvt.rn.f16x2.f32 %0, %1, %2;" : "=r"(h2[j]) : "f"(b), "f"(a));
            }
            op[g] = make_uint4(h2[0], h2[1], h2[2], h2[3]);
        }
    }
}

__global__ void repack_elw_kernel(const float* __restrict__ elw, float* __restrict__ out)
{
    const int N = FLAT * LC;
    for (int i = blockIdx.x * blockDim.x + threadIdx.x; i < N; i += gridDim.x * blockDim.x) {
        int fp = i / LC, l = i % LC;
        int pix = fp / 32, c = fp % 32;
        out[i] = elw[((size_t)(c * 484 + pix)) * LC + l];
    }
}

// ---------------- encoder split-K: blockIdx.y = quarter of FLAT ----------------
__global__ __launch_bounds__(256)
void encoder_kernel(const __half* __restrict__ h, const float* __restrict__ elwr,
                    float* __restrict__ z1p)
{
    __shared__ float sw[128 * LC];
    __shared__ float sc[16 * 128];
    const int tid = threadIdx.x;
    const int n0  = blockIdx.x * 16;
    const int ks  = blockIdx.y;
    const int nl  = tid / LC;
    const int l   = tid % LC;

    const int c0 = ks * 30;
    const int c1 = (ks == 3) ? 121 : c0 + 30;

    float acc = 0.f;
    for (int ch = c0; ch < c1; ch++) {
        const int fc = ch * 128;
        __syncthreads();
        for (int i = tid; i < 128 * LC; i += 256) sw[i] = elwr[(size_t)fc * LC + i];
        for (int i = tid; i < 16 * 128; i += 256) {
            int nn = i / 128, ff = i % 128;
            sc[i] = __half2float(h[(size_t)(n0 + nn) * FLAT + fc + ff]);
        }
        __syncthreads();
#pragma unroll 8
        for (int ff = 0; ff < 128; ff++)
            acc = fmaf(sc[nl * 128 + ff], sw[ff * LC + l], acc);
    }
    z1p[(size_t)ks * BATCH * LC + (n0 + nl) * LC + l] = acc;
}

__global__ __launch_bounds__(256)
void encoder_combine(const float* __restrict__ z1p, const float* __restrict__ elb,
                     float* __restrict__ z1)
{
    const int i = blockIdx.x * blockDim.x + threadIdx.x;
    if (i < BATCH * LC) {
        float a = z1p[i] + z1p[BATCH*LC + i] + z1p[2*BATCH*LC + i] + z1p[3*BATCH*LC + i];
        z1[i] = a + elb[i % LC];
    }
}

// ---------------- decoder v1 (writes g_h5) ----------------
__global__ __launch_bounds__(128)
void decoder_kernel(const float* __restrict__ z1, const float* __restrict__ dlw,
                    const float* __restrict__ dlb, __half* __restrict__ d)
{
    __shared__ float zs[16 * LC];
    const int tid = threadIdx.x;
    const int f   = blockIdx.x * 128 + tid;
    const int n0  = blockIdx.y * 16;

    for (int i = tid; i < 16 * LC; i += 128) zs[i] = z1[n0 * LC + i];
    __syncthreads();

    float wv[LC];
#pragma unroll
    for (int l = 0; l < LC; l++) wv[l] = dlw[(size_t)l * FLAT + f];
    const float bb = dlb[f];
    const int c = f / 484, pix = f % 484;
    const int py = pix / 22 + 2, px = pix % 22 + 2;

#pragma unroll
    for (int nn = 0; nn < 16; nn++) {
        float a = bb;
#pragma unroll
        for (int l = 0; l < LC; l++) a = fmaf(zs[nn * LC + l], wv[l], a);
        d[(((size_t)(n0 + nn) * 26 + py) * 26 + px) * 32 + c] = __float2half(tanha(a));
    }
}

// ---------------- hypernetwork tables ----------------
__global__ void hyper_kernel(const float* __restrict__ h1w, const float* __restrict__ h1b,
                             const float* __restrict__ h2w, const float* __restrict__ h2b,
                             const float* __restrict__ h3w, const float* __restrict__ h3b)
{
    const int j = blockIdx.x;
    const int w = threadIdx.x;
    const float t = 10.0f - 0.25f * (float)j;

    __shared__ float p1[HID], p2[HID];
    __shared__ float Wl[BLK], Ul[BLK];

    p1[w] = tanhf(t * h1w[w] + h1b[w]);
    __syncthreads();
    {
        float a = h2b[w];
#pragma unroll 8
        for (int k = 0; k < HID; k++) a = fmaf(p1[k], h2w[k * HID + w], a);
        p2[w] = tanhf(a);
    }
    __syncthreads();

    for (int o = w; o < OUT3; o += HID) {
        float a = h3b[o];
#pragma unroll 8
        for (int k = 0; k < HID; k++) a = fmaf(p2[k], h3w[(size_t)k * OUT3 + o], a);
        if (o < BLK)           Wl[o] = a;
        else if (o < 2 * BLK)  Ul[o - BLK] = a;
        else if (o < 3 * BLK)  Ul[o - 2 * BLK] *= 1.0f / (1.0f + expf(-a));
        else                   g_Bb[j * WID + (o - 3 * BLK)] = a;
    }
    __syncthreads();

    for (int o = w; o < BLK; o += HID) {
        int ww = o / LC, d = o % LC;
        g_W[j * BLK + d * WID + ww] = Wl[o];
        g_U[j * BLK + d * WID + ww] = Ul[o];
    }
    {
        float sv = 0.f;
#pragma unroll
        for (int d = 0; d < LC; d++) sv = fmaf(Wl[w * LC + d], Ul[w * LC + d], sv);
        g_s[j * WID + w] = sv;
    }
}

// ---------------- CNF RK4: 32 lanes per sample ----------------
__device__ __forceinline__ void feval32(int j, int lane, const float z[LC],
                                        float dz[LC], float& dl)
{
    const float* __restrict__ W  = g_W  + j * BLK;
    const float* __restrict__ U  = g_U  + j * BLK;
    const float* __restrict__ Bb = g_Bb + j * WID;
    const float* __restrict__ s  = g_s  + j * WID;
#pragma unroll
    for (int d = 0; d < LC; d++) dz[d] = 0.f;
    float tr = 0.f;
#pragma unroll
    for (int k = 0; k < 2; k++) {
        const int w = lane + k * 32;
        float a = Bb[w];
#pragma unroll
        for (int d = 0; d < LC; d++) a = fmaf(z[d], W[d * WID + w], a);
        float hh = tanhf(a);
#pragma unroll
        for (int d = 0; d < LC; d++) dz[d] = fmaf(hh, U[d * WID + w], dz[d]);
        tr = fmaf(1.0f - hh * hh, s[w], tr);
    }
#pragma unroll
    for (int off = 16; off > 0; off >>= 1) {
#pragma unroll
        for (int d = 0; d < LC; d++)
            dz[d] += __shfl_xor_sync(0xffffffffu, dz[d], off);
        tr += __shfl_xor_sync(0xffffffffu, tr, off);
    }
    const float inv = 1.0f / (float)WID;
#pragma unroll
    for (int d = 0; d < LC; d++) dz[d] *= inv;
    dl = -tr * inv;
}

__global__ __launch_bounds__(256)
void cnf_kernel(const float* __restrict__ z1, float* __restrict__ val)
{
    const int tid  = threadIdx.x;
    const int lane = tid & 31;
    const int n    = blockIdx.x * 8 + (tid >> 5);

    float z[LC];
#pragma unroll
    for (int d = 0; d < LC; d++) z[d] = z1[n * LC + d];
    float lp = 0.f;
    const float dt = -0.5f;

    for (int i = 0; i < NSTEP; i++) {
        float kz[LC], zt[LC], acc[LC];
        float l1, li, lacc;

        feval32(2 * i, lane, z, kz, l1);
        lacc = l1;
#pragma unroll
        for (int d = 0; d < LC; d++) { acc[d] = kz[d]; zt[d] = fmaf(0.5f * dt, kz[d], z[d]); }

        feval32(2 * i + 1, lane, zt, kz, li);
        lacc += 2.f * li;
#pragma unroll
        for (int d = 0; d < LC; d++) { acc[d] += 2.f * kz[d]; zt[d] = fmaf(0.5f * dt, kz[d], z[d]); }

        feval32(2 * i + 1, lane, zt, kz, li);
        lacc += 2.f * li;
#pragma unroll
        for (int d = 0; d < LC; d++) { acc[d] += 2.f * kz[d]; zt[d] = fmaf(dt, kz[d], z[d]); }

        feval32(2 * i + 2, lane, zt, kz, li);
        lacc += li;
#pragma unroll
        for (int d = 0; d < LC; d++) z[d] = fmaf(dt / 6.0f, acc[d] + kz[d], z[d]);
        lp = fmaf(dt / 6.0f, lacc, lp);
    }

    if (lane == 0) {
        float ss = 0.f;
#pragma unroll
        for (int d = 0; d < LC; d++) ss = fmaf(z[d], z[d], ss);
        const float c = (float)LC * 1.8378770664093453f + (float)LC * logf(0.1f);
        float logp = -0.5f * (c + ss * 10.0f);
        val[n] = logp - lp;
    }
}

__global__ __launch_bounds__(256)
void finalize_kernel(const float* __restrict__ val, float* __restrict__ outp)
{
    __shared__ float sm[256];
    const int tid = threadIdx.x;
    float a = 0.f;
    for (int i = tid; i < BATCH; i += 256) a += val[i];
    sm[tid] = a;
    __syncthreads();
    for (int s = 128; s > 0; s >>= 1) {
        if (tid < s) sm[tid] += sm[tid + s];
        __syncthreads();
    }
    if (tid == 0) outp[0] = sm[0] / (float)BATCH;
}

// ---------------- launcher ----------------
extern "C" void kernel_launch(void* const* d_in, const int* in_sizes, int n_in,
                              void* d_out, int out_size)
{
    const float* x   = (const float*)d_in[0];
    const float* c0w = (const float*)d_in[1];
    const float* c0b = (const float*)d_in[2];
    const float* c1w = (const float*)d_in[3];
    const float* c1b = (const float*)d_in[4];
    const float* c2w = (const float*)d_in[5];
    const float* c2b = (const float*)d_in[6];
    const float* elw = (const float*)d_in[7];
    const float* elb = (const float*)d_in[8];
    const float* dlw = (const float*)d_in[9];
    const float* dlb = (const float*)d_in[10];
    const float* t0w = (const float*)d_in[11];
    const float* t0b = (const float*)d_in[12];
    const float* t1w = (const float*)d_in[13];
    const float* t1b = (const float*)d_in[14];
    const float* t2w = (const float*)d_in[15];
    const float* t2b = (const float*)d_in[16];
    const float* h1w = (const float*)d_in[17];
    const float* h1b = (const float*)d_in[18];
    const float* h2w = (const float*)d_in[19];
    const float* h2b = (const float*)d_in[20];
    const float* h3w = (const float*)d_in[21];
    const float* h3b = (const float*)d_in[22];
    float* out = (float*)d_out;

    __half *h0, *h1, *h2, *h3, *h4, *h5;
    float *z1, *z1p, *val, *elwr;
    cudaGetSymbolAddress((void**)&h0, g_h0);
    cudaGetSymbolAddress((void**)&h1, g_h1);
    cudaGetSymbolAddress((void**)&h2, g_h2);
    cudaGetSymbolAddress((void**)&h3, g_h3);
    cudaGetSymbolAddress((void**)&h4, g_h4);
    cudaGetSymbolAddress((void**)&h5, g_h5);
    cudaGetSymbolAddress((void**)&z1,  g_z1);
    cudaGetSymbolAddress((void**)&z1p, g_z1p);
    cudaGetSymbolAddress((void**)&val, g_val);
    cudaGetSymbolAddress((void**)&elwr, g_elwr);

    // lazy-create side stream + events ONCE (first call runs outside capture)
    static cudaStream_t s2 = nullptr;
    static cudaEvent_t evS = nullptr, evZ = nullptr, evC = nullptr;
    if (!s2) {
        cudaStreamCreateWithFlags(&s2, cudaStreamNonBlocking);
        cudaEventCreateWithFlags(&evS, cudaEventDisableTiming);
        cudaEventCreateWithFlags(&evZ, cudaEventDisableTiming);
        cudaEventCreateWithFlags(&evC, cudaEventDisableTiming);
    }

    // fork: hyper runs on s2 concurrently with encoder conv stack
    cudaEventRecord(evS, 0);
    cudaStreamWaitEvent(s2, evS, 0);
    hyper_kernel<<<NTAB, HID, 0, s2>>>(h1w, h1b, h2w, h2b, h3w, h3b);

    // main stream: encoder path
    repack_elw_kernel<<<256, 256>>>(elw, elwr);
    conv0_kernel<<<BATCH, 256>>>(x, c0w, c0b, h0);
    run_gemm<26,26,24,24, 24,24,0, false,false>(h0, c1w, c1b, h1, 0);
    run_gemm<24,24,22,22, 22,22,0, false,false>(h1, c2w, c2b, h2, 0);
    encoder_kernel<<<dim3(BATCH/16, 4), 256>>>(h2, elwr, z1p);
    encoder_combine<<<(BATCH*LC + 255)/256, 256>>>(z1p, elb, z1);
    cudaEventRecord(evZ, 0);

    // side stream: CNF (needs z1 + hyper tables) + finalize, overlaps decoder path
    cudaStreamWaitEvent(s2, evZ, 0);
    cnf_kernel<<<BATCH/8, 256, 0, s2>>>(z1, val);
    finalize_kernel<<<1, 256, 0, s2>>>(val, out + (size_t)BATCH*IMG*IMG);
    cudaEventRecord(evC, s2);

    // main stream: decoder path
    decoder_kernel<<<dim3(FLAT/128, BATCH/16), 128>>>(z1, dlw, dlb, h5);
    run_gemm<26,26,24,24, 28,28,2, true,false>(h5, t0w, t0b, h3, 0);
    run_gemm<28,28,26,26, 30,30,2, true,false>(h3, t1w, t1b, h4, 0);
    run_gemm<30,30,28,28, 0,0,0,   true,true >(h4, t2w, t2b, out, 0);

    // join
    cudaStreamWaitEvent(0, evC, 0);
}